// round 1
// baseline (speedup 1.0000x reference)
#include <cuda_runtime.h>
#include <math.h>

#define MAXN 50000
#define HH 256

// Scratch (no allocations allowed anywhere).
__device__ float g_agg[(size_t)MAXN * HH];   // mean-aggregation accumulator
__device__ float g_h1[(size_t)MAXN * HH];    // layer-0 output (post-relu)
__device__ float g_deg[MAXN];
__device__ float g_deginv[MAXN];
__device__ float g_normsq;

// ---------------------------------------------------------------------------
// degree count + inverse
// ---------------------------------------------------------------------------
__global__ void deg_kernel(const int* __restrict__ edst, int E) {
    int e = blockIdx.x * blockDim.x + threadIdx.x;
    if (e < E) atomicAdd(&g_deg[edst[e]], 1.0f);
}

__global__ void deginv_kernel(int N) {
    int i = blockIdx.x * blockDim.x + threadIdx.x;
    if (i < N) g_deginv[i] = 1.0f / fmaxf(g_deg[i], 1.0f);
}

// ---------------------------------------------------------------------------
// edge aggregation: g_agg[dst] += feat[src]  (64 threads/edge, float4 lanes)
// ---------------------------------------------------------------------------
template<bool USEIDX>
__global__ void agg_kernel(const float* __restrict__ feat,
                           const int* __restrict__ idx,
                           const int* __restrict__ esrc,
                           const int* __restrict__ edst, int E) {
    long long gid = (long long)blockIdx.x * blockDim.x + threadIdx.x;
    int e = (int)(gid >> 6);
    if (e >= E) return;
    int c = ((int)gid & 63) * 4;
    int s = __ldg(esrc + e);
    if (USEIDX) s = __ldg(idx + s);
    int d = __ldg(edst + e);
    float4 v = *reinterpret_cast<const float4*>(feat + (size_t)s * HH + c);
    float* p = g_agg + (size_t)d * HH + c;
    atomicAdd(p + 0, v.x);
    atomicAdd(p + 1, v.y);
    atomicAdd(p + 2, v.z);
    atomicAdd(p + 3, v.w);
}

// ---------------------------------------------------------------------------
// Fused SAGE layer GEMM:
//   C[row, n] = sum_k A_ext[row,k] * W_ext[k,n] + bias[n]   (K = 512)
//   A_ext[:, 0:256]   = Afeat[idx[row]]        (self features)
//   A_ext[:, 256:512] = g_agg[row] * deginv    (mean neighbor features)
//   W_ext[0:256]   = Wself,  W_ext[256:512] = Wneigh
// 128x128 tile, BK=16, 8x8 per thread, 256 threads.
// ---------------------------------------------------------------------------
template<bool USEIDX, bool RELU, bool SUMSQ>
__global__ __launch_bounds__(256, 2)
void sage_gemm(const float* __restrict__ Afeat, const int* __restrict__ idx,
               const float* __restrict__ Wself, const float* __restrict__ Wneigh,
               const float* __restrict__ bias, float* __restrict__ Cout, int N)
{
    __shared__ float As[16][132];   // [k][row], padded: 2-way max conflicts
    __shared__ float Bs[16][128];   // [k][col]

    const int tid = threadIdx.x;
    const int rowbase = blockIdx.y * 128;
    const int colbase = blockIdx.x * 128;
    const int rm = (tid >> 4) * 8;      // local row offset of 8-row strip
    const int rn = (tid & 15) * 8;      // local col offset of 8-col strip

    float acc[8][8];
    #pragma unroll
    for (int i = 0; i < 8; i++)
        #pragma unroll
        for (int j = 0; j < 8; j++) acc[i][j] = 0.0f;

    #pragma unroll 1
    for (int kt = 0; kt < 32; kt++) {
        const int k0 = kt * 16;
        const bool neigh = (k0 >= 256);

        // --- load A tile (128 rows x 16 k) ---
        #pragma unroll
        for (int l = 0; l < 2; l++) {
            int L = tid + l * 256;
            int r  = L >> 2;            // 0..127
            int kq = (L & 3) * 4;       // 0,4,8,12
            int row = rowbase + r;
            float4 v = make_float4(0.f, 0.f, 0.f, 0.f);
            if (row < N) {
                if (!neigh) {
                    int ar = USEIDX ? __ldg(idx + row) : row;
                    v = *reinterpret_cast<const float4*>(
                        Afeat + (size_t)ar * 256 + (k0 + kq));
                } else {
                    v = *reinterpret_cast<const float4*>(
                        g_agg + (size_t)row * 256 + (k0 - 256 + kq));
                    float dv = g_deginv[row];
                    v.x *= dv; v.y *= dv; v.z *= dv; v.w *= dv;
                }
            }
            As[kq + 0][r] = v.x;
            As[kq + 1][r] = v.y;
            As[kq + 2][r] = v.z;
            As[kq + 3][r] = v.w;
        }

        // --- load B tile (16 k x 128 n) ---
        {
            const float* W = neigh ? Wneigh : Wself;
            int kb = neigh ? (k0 - 256) : k0;
            #pragma unroll
            for (int l = 0; l < 2; l++) {
                int L = tid + l * 256;
                int kc = L >> 5;             // 0..15
                int n  = (L & 31) * 4;       // 0..124
                float4 v = *reinterpret_cast<const float4*>(
                    W + (size_t)(kb + kc) * 256 + colbase + n);
                *reinterpret_cast<float4*>(&Bs[kc][n]) = v;
            }
        }
        __syncthreads();

        // --- FMA ---
        #pragma unroll
        for (int kc = 0; kc < 16; kc++) {
            float a[8], b[8];
            *(float4*)&a[0] = *(const float4*)&As[kc][rm];
            *(float4*)&a[4] = *(const float4*)&As[kc][rm + 4];
            *(float4*)&b[0] = *(const float4*)&Bs[kc][rn];
            *(float4*)&b[4] = *(const float4*)&Bs[kc][rn + 4];
            #pragma unroll
            for (int i = 0; i < 8; i++)
                #pragma unroll
                for (int j = 0; j < 8; j++)
                    acc[i][j] = fmaf(a[i], b[j], acc[i][j]);
        }
        __syncthreads();
    }

    // --- epilogue: bias (+relu) (+sumsq) + store ---
    float bv[8];
    *(float4*)&bv[0] = *(const float4*)(bias + colbase + rn);
    *(float4*)&bv[4] = *(const float4*)(bias + colbase + rn + 4);

    float ss = 0.0f;
    #pragma unroll
    for (int i = 0; i < 8; i++) {
        int row = rowbase + rm + i;
        if (row < N) {
            float v[8];
            #pragma unroll
            for (int j = 0; j < 8; j++) {
                float x = acc[i][j] + bv[j];
                if (RELU) x = fmaxf(x, 0.0f);
                v[j] = x;
                if (SUMSQ) ss = fmaf(x, x, ss);
            }
            float* dst = Cout + (size_t)row * 256 + colbase + rn;
            *reinterpret_cast<float4*>(dst)     = *(float4*)&v[0];
            *reinterpret_cast<float4*>(dst + 4) = *(float4*)&v[4];
        }
    }

    if (SUMSQ) {
        #pragma unroll
        for (int off = 16; off; off >>= 1)
            ss += __shfl_down_sync(0xffffffffu, ss, off);
        if ((tid & 31) == 0) atomicAdd(&g_normsq, ss);
    }
}

// ---------------------------------------------------------------------------
// final global-norm scale, in place on d_out
// ---------------------------------------------------------------------------
__global__ void scale_kernel(float* __restrict__ out, long long total4) {
    float s = 1.0f / sqrtf(g_normsq);
    long long stride = (long long)gridDim.x * blockDim.x;
    for (long long i = (long long)blockIdx.x * blockDim.x + threadIdx.x;
         i < total4; i += stride) {
        float4 v = reinterpret_cast<float4*>(out)[i];
        v.x *= s; v.y *= s; v.z *= s; v.w *= s;
        reinterpret_cast<float4*>(out)[i] = v;
    }
}

// ---------------------------------------------------------------------------
extern "C" void kernel_launch(void* const* d_in, const int* in_sizes, int n_in,
                              void* d_out, int out_size) {
    const int*   input_nodes = (const int*)  d_in[0];
    const int*   esrc        = (const int*)  d_in[1];
    const int*   edst        = (const int*)  d_in[2];
    const float* emb         = (const float*)d_in[3];
    const float* Ws0         = (const float*)d_in[4];
    const float* Wn0         = (const float*)d_in[5];
    const float* b0          = (const float*)d_in[6];
    const float* Ws1         = (const float*)d_in[7];
    const float* Wn1         = (const float*)d_in[8];
    const float* b1          = (const float*)d_in[9];

    int N = in_sizes[0];
    int E = in_sizes[1];
    float* out = (float*)d_out;

    void *p_agg, *p_deg, *p_norm, *p_h1;
    cudaGetSymbolAddress(&p_agg,  g_agg);
    cudaGetSymbolAddress(&p_deg,  g_deg);
    cudaGetSymbolAddress(&p_norm, g_normsq);
    cudaGetSymbolAddress(&p_h1,   g_h1);
    float* h1 = (float*)p_h1;

    cudaMemsetAsync(p_deg,  0, (size_t)N * sizeof(float), 0);
    cudaMemsetAsync(p_agg,  0, (size_t)N * HH * sizeof(float), 0);
    cudaMemsetAsync(p_norm, 0, sizeof(float), 0);

    deg_kernel<<<(E + 255) / 256, 256>>>(edst, E);
    deginv_kernel<<<(N + 255) / 256, 256>>>(N);

    long long aggT = (long long)E * 64;
    int aggB = (int)((aggT + 255) / 256);
    agg_kernel<true><<<aggB, 256>>>(emb, input_nodes, esrc, edst, E);

    dim3 ggrid(2, (N + 127) / 128);
    sage_gemm<true, true, false><<<ggrid, 256>>>(emb, input_nodes, Ws0, Wn0, b0, h1, N);

    cudaMemsetAsync(p_agg, 0, (size_t)N * HH * sizeof(float), 0);
    agg_kernel<false><<<aggB, 256>>>(h1, nullptr, esrc, edst, E);

    sage_gemm<false, false, true><<<ggrid, 256>>>(h1, nullptr, Ws1, Wn1, b1, out, N);

    long long total4 = ((long long)N * HH) / 4;
    scale_kernel<<<2048, 256>>>(out, total4);
}

// round 2
// speedup vs baseline: 2.5951x; 2.5951x over previous
#include <cuda_runtime.h>
#include <math.h>

#define MAXN 50000
#define MAXE 1600000
#define HH 256

// Scratch (no allocations allowed anywhere).
__device__ float g_agg[(size_t)MAXN * HH];   // mean-aggregated neighbor feats
__device__ float g_h1[(size_t)MAXN * HH];    // layer-0 output (post-relu)
__device__ int   g_cnt[MAXN];                // degree histogram
__device__ int   g_rowptr[MAXN + 1];         // CSR row pointers
__device__ int   g_cursor[MAXN];             // scatter cursors
__device__ int   g_csr_src[MAXE];            // CSR column (src) indices
__device__ float g_deginv[MAXN];
__device__ float g_normsq;

// ---------------------------------------------------------------------------
// CSR build: histogram -> scan -> scatter
// ---------------------------------------------------------------------------
__global__ void hist_kernel(const int* __restrict__ edst, int E) {
    int e = blockIdx.x * blockDim.x + threadIdx.x;
    if (e < E) atomicAdd(&g_cnt[edst[e]], 1);
}

// single-block inclusive->exclusive scan over g_cnt into g_rowptr
__global__ void scan_kernel(int N) {
    __shared__ int sh[1024];
    __shared__ int carry_s;
    if (threadIdx.x == 0) carry_s = 0;
    __syncthreads();
    for (int base = 0; base < N; base += 1024) {
        int i = base + threadIdx.x;
        int v = (i < N) ? g_cnt[i] : 0;
        sh[threadIdx.x] = v;
        __syncthreads();
        #pragma unroll
        for (int off = 1; off < 1024; off <<= 1) {
            int t = (threadIdx.x >= off) ? sh[threadIdx.x - off] : 0;
            __syncthreads();
            sh[threadIdx.x] += t;
            __syncthreads();
        }
        int carry = carry_s;
        if (i < N) {
            g_rowptr[i] = carry + sh[threadIdx.x] - v;   // exclusive
            g_deginv[i] = 1.0f / fmaxf((float)v, 1.0f);
        }
        __syncthreads();
        if (threadIdx.x == 0) carry_s = carry + sh[1023];
        __syncthreads();
    }
    if (threadIdx.x == 0) g_rowptr[N] = carry_s;
}

__global__ void fill_kernel(const int* __restrict__ esrc,
                            const int* __restrict__ edst, int E) {
    int e = blockIdx.x * blockDim.x + threadIdx.x;
    if (e < E) {
        int d = edst[e];
        int pos = atomicAdd(&g_cursor[d], 1);
        g_csr_src[pos] = esrc[e];
    }
}

// ---------------------------------------------------------------------------
// Gather-based mean aggregation: g_agg[n] = mean_{s in nbr(n)} feat[s]
// 64 threads per node (float4 lanes), 4 nodes per 256-thread block.
// ---------------------------------------------------------------------------
template<bool USEIDX>
__global__ __launch_bounds__(256, 8)
void agg_gather(const float* __restrict__ feat, const int* __restrict__ idx,
                int N)
{
    int node = blockIdx.x * 4 + (threadIdx.x >> 6);
    if (node >= N) return;
    int c = (threadIdx.x & 63) * 4;

    int b = g_rowptr[node];
    int e = g_rowptr[node + 1];

    float4 acc = make_float4(0.f, 0.f, 0.f, 0.f);
    int i = b;
    for (; i + 4 <= e; i += 4) {
        int s0 = g_csr_src[i + 0];
        int s1 = g_csr_src[i + 1];
        int s2 = g_csr_src[i + 2];
        int s3 = g_csr_src[i + 3];
        if (USEIDX) { s0 = __ldg(idx + s0); s1 = __ldg(idx + s1);
                      s2 = __ldg(idx + s2); s3 = __ldg(idx + s3); }
        float4 v0 = *reinterpret_cast<const float4*>(feat + (size_t)s0 * HH + c);
        float4 v1 = *reinterpret_cast<const float4*>(feat + (size_t)s1 * HH + c);
        float4 v2 = *reinterpret_cast<const float4*>(feat + (size_t)s2 * HH + c);
        float4 v3 = *reinterpret_cast<const float4*>(feat + (size_t)s3 * HH + c);
        acc.x += (v0.x + v1.x) + (v2.x + v3.x);
        acc.y += (v0.y + v1.y) + (v2.y + v3.y);
        acc.z += (v0.z + v1.z) + (v2.z + v3.z);
        acc.w += (v0.w + v1.w) + (v2.w + v3.w);
    }
    for (; i < e; i++) {
        int s = g_csr_src[i];
        if (USEIDX) s = __ldg(idx + s);
        float4 v = *reinterpret_cast<const float4*>(feat + (size_t)s * HH + c);
        acc.x += v.x; acc.y += v.y; acc.z += v.z; acc.w += v.w;
    }

    float dv = g_deginv[node];
    acc.x *= dv; acc.y *= dv; acc.z *= dv; acc.w *= dv;
    *reinterpret_cast<float4*>(g_agg + (size_t)node * HH + c) = acc;
}

// ---------------------------------------------------------------------------
// Fused SAGE layer GEMM: C = [self | mean-agg] @ [Wself ; Wneigh] + bias
// 128x128 tile, BK=16, 8x8 per thread, 256 threads.
// ---------------------------------------------------------------------------
template<bool USEIDX, bool RELU, bool SUMSQ>
__global__ __launch_bounds__(256, 2)
void sage_gemm(const float* __restrict__ Afeat, const int* __restrict__ idx,
               const float* __restrict__ Wself, const float* __restrict__ Wneigh,
               const float* __restrict__ bias, float* __restrict__ Cout, int N)
{
    __shared__ float As[16][132];
    __shared__ float Bs[16][128];

    const int tid = threadIdx.x;
    const int rowbase = blockIdx.y * 128;
    const int colbase = blockIdx.x * 128;
    const int rm = (tid >> 4) * 8;
    const int rn = (tid & 15) * 8;

    float acc[8][8];
    #pragma unroll
    for (int i = 0; i < 8; i++)
        #pragma unroll
        for (int j = 0; j < 8; j++) acc[i][j] = 0.0f;

    #pragma unroll 1
    for (int kt = 0; kt < 32; kt++) {
        const int k0 = kt * 16;
        const bool neigh = (k0 >= 256);

        #pragma unroll
        for (int l = 0; l < 2; l++) {
            int L = tid + l * 256;
            int r  = L >> 2;
            int kq = (L & 3) * 4;
            int row = rowbase + r;
            float4 v = make_float4(0.f, 0.f, 0.f, 0.f);
            if (row < N) {
                if (!neigh) {
                    int ar = USEIDX ? __ldg(idx + row) : row;
                    v = *reinterpret_cast<const float4*>(
                        Afeat + (size_t)ar * 256 + (k0 + kq));
                } else {
                    v = *reinterpret_cast<const float4*>(
                        g_agg + (size_t)row * 256 + (k0 - 256 + kq));
                }
            }
            As[kq + 0][r] = v.x;
            As[kq + 1][r] = v.y;
            As[kq + 2][r] = v.z;
            As[kq + 3][r] = v.w;
        }

        {
            const float* W = neigh ? Wneigh : Wself;
            int kb = neigh ? (k0 - 256) : k0;
            #pragma unroll
            for (int l = 0; l < 2; l++) {
                int L = tid + l * 256;
                int kc = L >> 5;
                int n  = (L & 31) * 4;
                float4 v = *reinterpret_cast<const float4*>(
                    W + (size_t)(kb + kc) * 256 + colbase + n);
                *reinterpret_cast<float4*>(&Bs[kc][n]) = v;
            }
        }
        __syncthreads();

        #pragma unroll
        for (int kc = 0; kc < 16; kc++) {
            float a[8], b[8];
            *(float4*)&a[0] = *(const float4*)&As[kc][rm];
            *(float4*)&a[4] = *(const float4*)&As[kc][rm + 4];
            *(float4*)&b[0] = *(const float4*)&Bs[kc][rn];
            *(float4*)&b[4] = *(const float4*)&Bs[kc][rn + 4];
            #pragma unroll
            for (int i = 0; i < 8; i++)
                #pragma unroll
                for (int j = 0; j < 8; j++)
                    acc[i][j] = fmaf(a[i], b[j], acc[i][j]);
        }
        __syncthreads();
    }

    float bv[8];
    *(float4*)&bv[0] = *(const float4*)(bias + colbase + rn);
    *(float4*)&bv[4] = *(const float4*)(bias + colbase + rn + 4);

    float ss = 0.0f;
    #pragma unroll
    for (int i = 0; i < 8; i++) {
        int row = rowbase + rm + i;
        if (row < N) {
            float v[8];
            #pragma unroll
            for (int j = 0; j < 8; j++) {
                float x = acc[i][j] + bv[j];
                if (RELU) x = fmaxf(x, 0.0f);
                v[j] = x;
                if (SUMSQ) ss = fmaf(x, x, ss);
            }
            float* dst = Cout + (size_t)row * 256 + colbase + rn;
            *reinterpret_cast<float4*>(dst)     = *(float4*)&v[0];
            *reinterpret_cast<float4*>(dst + 4) = *(float4*)&v[4];
        }
    }

    if (SUMSQ) {
        #pragma unroll
        for (int off = 16; off; off >>= 1)
            ss += __shfl_down_sync(0xffffffffu, ss, off);
        if ((tid & 31) == 0) atomicAdd(&g_normsq, ss);
    }
}

// ---------------------------------------------------------------------------
__global__ void scale_kernel(float* __restrict__ out, long long total4) {
    float s = 1.0f / sqrtf(g_normsq);
    long long stride = (long long)gridDim.x * blockDim.x;
    for (long long i = (long long)blockIdx.x * blockDim.x + threadIdx.x;
         i < total4; i += stride) {
        float4 v = reinterpret_cast<float4*>(out)[i];
        v.x *= s; v.y *= s; v.z *= s; v.w *= s;
        reinterpret_cast<float4*>(out)[i] = v;
    }
}

// ---------------------------------------------------------------------------
extern "C" void kernel_launch(void* const* d_in, const int* in_sizes, int n_in,
                              void* d_out, int out_size) {
    const int*   input_nodes = (const int*)  d_in[0];
    const int*   esrc        = (const int*)  d_in[1];
    const int*   edst        = (const int*)  d_in[2];
    const float* emb         = (const float*)d_in[3];
    const float* Ws0         = (const float*)d_in[4];
    const float* Wn0         = (const float*)d_in[5];
    const float* b0          = (const float*)d_in[6];
    const float* Ws1         = (const float*)d_in[7];
    const float* Wn1         = (const float*)d_in[8];
    const float* b1          = (const float*)d_in[9];

    int N = in_sizes[0];
    int E = in_sizes[1];
    float* out = (float*)d_out;

    void *p_cnt, *p_norm, *p_h1, *p_rowptr, *p_cursor;
    cudaGetSymbolAddress(&p_cnt,    g_cnt);
    cudaGetSymbolAddress(&p_norm,   g_normsq);
    cudaGetSymbolAddress(&p_h1,     g_h1);
    cudaGetSymbolAddress(&p_rowptr, g_rowptr);
    cudaGetSymbolAddress(&p_cursor, g_cursor);
    float* h1 = (float*)p_h1;

    cudaMemsetAsync(p_cnt,  0, (size_t)N * sizeof(int), 0);
    cudaMemsetAsync(p_norm, 0, sizeof(float), 0);

    // CSR build (reused by both layers)
    hist_kernel<<<(E + 255) / 256, 256>>>(edst, E);
    scan_kernel<<<1, 1024>>>(N);
    cudaMemcpyAsync(p_cursor, p_rowptr, (size_t)N * sizeof(int),
                    cudaMemcpyDeviceToDevice, 0);
    fill_kernel<<<(E + 255) / 256, 256>>>(esrc, edst, E);

    dim3 ggrid(2, (N + 127) / 128);
    int aggB = (N + 3) / 4;

    // layer 0
    agg_gather<true><<<aggB, 256>>>(emb, input_nodes, N);
    sage_gemm<true, true, false><<<ggrid, 256>>>(emb, input_nodes, Ws0, Wn0, b0, h1, N);

    // layer 1
    agg_gather<false><<<aggB, 256>>>(h1, nullptr, N);
    sage_gemm<false, false, true><<<ggrid, 256>>>(h1, nullptr, Ws1, Wn1, b1, out, N);

    long long total4 = ((long long)N * HH) / 4;
    scale_kernel<<<2048, 256>>>(out, total4);
}

// round 5
// speedup vs baseline: 4.8575x; 1.8718x over previous
#include <cuda_runtime.h>
#include <math.h>
#include <stdint.h>

#define MAXN 50000
#define MAXE 1600000
#define HH 256

// ---------------------------------------------------------------------------
// Scratch (no allocations allowed anywhere).
// ---------------------------------------------------------------------------
__device__ float g_agg[(size_t)MAXN * HH];    // mean-aggregated neighbor feats
__device__ float g_h1[(size_t)MAXN * HH];     // layer-0 output (post-relu)
__device__ int   g_cnt[MAXN];
__device__ int   g_rowptr[MAXN + 1];
__device__ int   g_cursor[MAXN];
__device__ int   g_csr_src[MAXE];
__device__ float g_deginv[MAXN];
__device__ float g_normsq;
// Transposed tf32-rounded weights: Wt[n][k], n=0..255, k=0..511
__device__ float g_Wt0[256 * 512];
__device__ float g_Wt1[256 * 512];

__device__ __forceinline__ float tf32r(float x) {
    uint32_t u;
    asm("cvt.rna.tf32.f32 %0, %1;" : "=r"(u) : "f"(x));
    return __uint_as_float(u);
}

__device__ __forceinline__ void mma_tf32(float& c0, float& c1, float& c2, float& c3,
                                         uint32_t a0, uint32_t a1, uint32_t a2, uint32_t a3,
                                         uint32_t b0, uint32_t b1) {
    asm volatile(
        "mma.sync.aligned.m16n8k8.row.col.f32.tf32.tf32.f32 "
        "{%0,%1,%2,%3}, {%4,%5,%6,%7}, {%8,%9}, {%0,%1,%2,%3};"
        : "+f"(c0), "+f"(c1), "+f"(c2), "+f"(c3)
        : "r"(a0), "r"(a1), "r"(a2), "r"(a3), "r"(b0), "r"(b1));
}

// ---------------------------------------------------------------------------
// CSR build
// ---------------------------------------------------------------------------
__global__ void hist_kernel(const int* __restrict__ edst, int E) {
    int e = blockIdx.x * blockDim.x + threadIdx.x;
    if (e < E) atomicAdd(&g_cnt[edst[e]], 1);
}

__global__ void scan_kernel(int N) {
    __shared__ int sh[1024];
    __shared__ int carry_s;
    if (threadIdx.x == 0) carry_s = 0;
    __syncthreads();
    for (int base = 0; base < N; base += 1024) {
        int i = base + threadIdx.x;
        int v = (i < N) ? g_cnt[i] : 0;
        sh[threadIdx.x] = v;
        __syncthreads();
        #pragma unroll
        for (int off = 1; off < 1024; off <<= 1) {
            int t = (threadIdx.x >= off) ? sh[threadIdx.x - off] : 0;
            __syncthreads();
            sh[threadIdx.x] += t;
            __syncthreads();
        }
        int carry = carry_s;
        if (i < N) {
            g_rowptr[i] = carry + sh[threadIdx.x] - v;
            g_deginv[i] = 1.0f / fmaxf((float)v, 1.0f);
        }
        __syncthreads();
        if (threadIdx.x == 0) carry_s = carry + sh[1023];
        __syncthreads();
    }
    if (threadIdx.x == 0) g_rowptr[N] = carry_s;
}

__global__ void fill_kernel(const int* __restrict__ esrc,
                            const int* __restrict__ edst, int E) {
    int e = blockIdx.x * blockDim.x + threadIdx.x;
    if (e < E) {
        int pos = atomicAdd(&g_cursor[edst[e]], 1);
        g_csr_src[pos] = esrc[e];
    }
}

// ---------------------------------------------------------------------------
// Weight transpose + tf32 rounding: Wt[n*512 + k] = tf32(Wext[k][n])
// ---------------------------------------------------------------------------
__global__ void wtrans_kernel(const float* __restrict__ Ws,
                              const float* __restrict__ Wn,
                              float* __restrict__ Wt) {
    int i = blockIdx.x * blockDim.x + threadIdx.x;   // 131072
    if (i >= 256 * 512) return;
    int n = i >> 9;
    int k = i & 511;
    float v = (k < 256) ? Ws[(size_t)k * 256 + n]
                        : Wn[(size_t)(k - 256) * 256 + n];
    Wt[i] = tf32r(v);
}

// ---------------------------------------------------------------------------
// Gather-based mean aggregation (unchanged from R2: 95us, L2-bound)
// ---------------------------------------------------------------------------
template<bool USEIDX>
__global__ __launch_bounds__(256, 8)
void agg_gather(const float* __restrict__ feat, const int* __restrict__ idx, int N)
{
    int node = blockIdx.x * 4 + (threadIdx.x >> 6);
    if (node >= N) return;
    int c = (threadIdx.x & 63) * 4;

    int b = g_rowptr[node];
    int e = g_rowptr[node + 1];

    float4 acc = make_float4(0.f, 0.f, 0.f, 0.f);
    int i = b;
    for (; i + 4 <= e; i += 4) {
        int s0 = g_csr_src[i + 0];
        int s1 = g_csr_src[i + 1];
        int s2 = g_csr_src[i + 2];
        int s3 = g_csr_src[i + 3];
        if (USEIDX) { s0 = __ldg(idx + s0); s1 = __ldg(idx + s1);
                      s2 = __ldg(idx + s2); s3 = __ldg(idx + s3); }
        float4 v0 = *reinterpret_cast<const float4*>(feat + (size_t)s0 * HH + c);
        float4 v1 = *reinterpret_cast<const float4*>(feat + (size_t)s1 * HH + c);
        float4 v2 = *reinterpret_cast<const float4*>(feat + (size_t)s2 * HH + c);
        float4 v3 = *reinterpret_cast<const float4*>(feat + (size_t)s3 * HH + c);
        acc.x += (v0.x + v1.x) + (v2.x + v3.x);
        acc.y += (v0.y + v1.y) + (v2.y + v3.y);
        acc.z += (v0.z + v1.z) + (v2.z + v3.z);
        acc.w += (v0.w + v1.w) + (v2.w + v3.w);
    }
    for (; i < e; i++) {
        int s = g_csr_src[i];
        if (USEIDX) s = __ldg(idx + s);
        float4 v = *reinterpret_cast<const float4*>(feat + (size_t)s * HH + c);
        acc.x += v.x; acc.y += v.y; acc.z += v.z; acc.w += v.w;
    }

    float dv = g_deginv[node];
    acc.x *= dv; acc.y *= dv; acc.z *= dv; acc.w *= dv;
    *reinterpret_cast<float4*>(g_agg + (size_t)node * HH + c) = acc;
}

// ---------------------------------------------------------------------------
// tf32 mma.sync fused SAGE GEMM.
//   C[128-tile, 128-tile] = [self | mean-agg] (K=512) @ W_ext + bias
// 256 threads = 8 warps (2x4), warp tile 64x32, mma m16n8k8, BK=32,
// double-buffered SMEM (stride 36 => conflict-free fragment LDS),
// register-staged prefetch of next K-chunk.
// ---------------------------------------------------------------------------
template<bool USEIDX, bool RELU, bool SUMSQ>
__global__ __launch_bounds__(256)
void sage_gemm_mma(const float* __restrict__ Afeat, const int* __restrict__ idx,
                   const float* __restrict__ Wt, const float* __restrict__ bias,
                   float* __restrict__ Cout, int N)
{
    extern __shared__ float sm[];

    const int tid  = threadIdx.x;
    const int wid  = tid >> 5;
    const int lane = tid & 31;
    const int g    = lane >> 2;       // groupID
    const int t    = lane & 3;        // threadID_in_group
    const int rowbase = blockIdx.y * 128;
    const int colbase = blockIdx.x * 128;

    const int wm = (wid >> 2) * 64;   // warp m offset (0 or 64)
    const int wn = (wid & 3) * 32;    // warp n offset (0,32,64,96)

    const int lr = tid >> 3;          // 0..31
    const int lq = tid & 7;           // float4 within 32-float row

    float c[4][4][4];
    #pragma unroll
    for (int mt = 0; mt < 4; mt++)
        #pragma unroll
        for (int nt = 0; nt < 4; nt++)
            #pragma unroll
            for (int j = 0; j < 4; j++) c[mt][nt][j] = 0.0f;

    int aoff[4], boff[4];
    #pragma unroll
    for (int mt = 0; mt < 4; mt++) aoff[mt] = (wm + mt * 16 + g) * 36 + t;
    #pragma unroll
    for (int nt = 0; nt < 4; nt++) boff[nt] = (wn + nt * 8 + g) * 36 + t;

    float4 aR[4], bR[4];

    auto load_tile = [&](int kt) {
        const int k0 = kt * 32;
        const bool neigh = (k0 >= 256);
        const float* src = neigh ? (const float*)g_agg : Afeat;
        const int kk = neigh ? (k0 - 256) : k0;
        #pragma unroll
        for (int i = 0; i < 4; i++) {
            int r = lr + i * 32;
            int row = rowbase + r;
            float4 v = make_float4(0.f, 0.f, 0.f, 0.f);
            if (row < N) {
                int ar = (!neigh && USEIDX) ? __ldg(idx + row) : row;
                v = *reinterpret_cast<const float4*>(src + (size_t)ar * 256 + kk + lq * 4);
            }
            aR[i] = v;
        }
        #pragma unroll
        for (int i = 0; i < 4; i++) {
            int r = lr + i * 32;
            bR[i] = *reinterpret_cast<const float4*>(
                Wt + (size_t)(colbase + r) * 512 + k0 + lq * 4);
        }
    };

    auto store_tile = [&](int buf) {
        float* SA = sm + buf * 4608;
        float* SB = sm + 9216 + buf * 4608;
        #pragma unroll
        for (int i = 0; i < 4; i++) {
            int r = lr + i * 32;
            float4 v = aR[i];
            v.x = tf32r(v.x); v.y = tf32r(v.y); v.z = tf32r(v.z); v.w = tf32r(v.w);
            *reinterpret_cast<float4*>(SA + r * 36 + lq * 4) = v;
        }
        #pragma unroll
        for (int i = 0; i < 4; i++) {
            int r = lr + i * 32;
            *reinterpret_cast<float4*>(SB + r * 36 + lq * 4) = bR[i];
        }
    };

    load_tile(0);
    store_tile(0);
    __syncthreads();

    #pragma unroll 1
    for (int kt = 0; kt < 16; kt++) {
        const int buf = kt & 1;
        if (kt + 1 < 16) load_tile(kt + 1);

        const float* SA = sm + buf * 4608;
        const float* SB = sm + 9216 + buf * 4608;

        #pragma unroll
        for (int ks = 0; ks < 4; ks++) {
            const int kb = ks * 8;
            uint32_t af[4][4], bf[4][2];
            #pragma unroll
            for (int mt = 0; mt < 4; mt++) {
                af[mt][0] = __float_as_uint(SA[aoff[mt] + kb]);
                af[mt][1] = __float_as_uint(SA[aoff[mt] + kb + 288]);   // +8 rows
                af[mt][2] = __float_as_uint(SA[aoff[mt] + kb + 4]);
                af[mt][3] = __float_as_uint(SA[aoff[mt] + kb + 292]);
            }
            #pragma unroll
            for (int nt = 0; nt < 4; nt++) {
                bf[nt][0] = __float_as_uint(SB[boff[nt] + kb]);
                bf[nt][1] = __float_as_uint(SB[boff[nt] + kb + 4]);
            }
            #pragma unroll
            for (int mt = 0; mt < 4; mt++)
                #pragma unroll
                for (int nt = 0; nt < 4; nt++)
                    mma_tf32(c[mt][nt][0], c[mt][nt][1], c[mt][nt][2], c[mt][nt][3],
                             af[mt][0], af[mt][1], af[mt][2], af[mt][3],
                             bf[nt][0], bf[nt][1]);
        }

        if (kt + 1 < 16) {
            store_tile((kt + 1) & 1);
            __syncthreads();
        }
    }

    // ---- epilogue ----
    float ss = 0.0f;
    #pragma unroll
    for (int nt = 0; nt < 4; nt++) {
        int col = colbase + wn + nt * 8 + 2 * t;
        float2 bv = *reinterpret_cast<const float2*>(bias + col);
        #pragma unroll
        for (int mt = 0; mt < 4; mt++) {
            int r0 = rowbase + wm + mt * 16 + g;
            float x0 = c[mt][nt][0] + bv.x;
            float x1 = c[mt][nt][1] + bv.y;
            float x2 = c[mt][nt][2] + bv.x;
            float x3 = c[mt][nt][3] + bv.y;
            if (RELU) { x0 = fmaxf(x0, 0.f); x1 = fmaxf(x1, 0.f);
                        x2 = fmaxf(x2, 0.f); x3 = fmaxf(x3, 0.f); }
            if (r0 < N) {
                *reinterpret_cast<float2*>(Cout + (size_t)r0 * 256 + col) =
                    make_float2(x0, x1);
                if (SUMSQ) { ss = fmaf(x0, x0, ss); ss = fmaf(x1, x1, ss); }
            }
            if (r0 + 8 < N) {
                *reinterpret_cast<float2*>(Cout + (size_t)(r0 + 8) * 256 + col) =
                    make_float2(x2, x3);
                if (SUMSQ) { ss = fmaf(x2, x2, ss); ss = fmaf(x3, x3, ss); }
            }
        }
    }

    if (SUMSQ) {
        #pragma unroll
        for (int off = 16; off; off >>= 1)
            ss += __shfl_down_sync(0xffffffffu, ss, off);
        if (lane == 0) atomicAdd(&g_normsq, ss);
    }
}

// ---------------------------------------------------------------------------
__global__ void scale_kernel(float* __restrict__ out, long long total4) {
    float s = 1.0f / sqrtf(g_normsq);
    long long stride = (long long)gridDim.x * blockDim.x;
    for (long long i = (long long)blockIdx.x * blockDim.x + threadIdx.x;
         i < total4; i += stride) {
        float4 v = reinterpret_cast<float4*>(out)[i];
        v.x *= s; v.y *= s; v.z *= s; v.w *= s;
        reinterpret_cast<float4*>(out)[i] = v;
    }
}

// ---------------------------------------------------------------------------
extern "C" void kernel_launch(void* const* d_in, const int* in_sizes, int n_in,
                              void* d_out, int out_size) {
    const int*   input_nodes = (const int*)  d_in[0];
    const int*   esrc        = (const int*)  d_in[1];
    const int*   edst        = (const int*)  d_in[2];
    const float* emb         = (const float*)d_in[3];
    const float* Ws0         = (const float*)d_in[4];
    const float* Wn0         = (const float*)d_in[5];
    const float* b0          = (const float*)d_in[6];
    const float* Ws1         = (const float*)d_in[7];
    const float* Wn1         = (const float*)d_in[8];
    const float* b1          = (const float*)d_in[9];

    int N = in_sizes[0];
    int E = in_sizes[1];
    float* out = (float*)d_out;

    void *p_cnt, *p_norm, *p_h1, *p_rowptr, *p_cursor, *p_w0, *p_w1;
    cudaGetSymbolAddress(&p_cnt,    g_cnt);
    cudaGetSymbolAddress(&p_norm,   g_normsq);
    cudaGetSymbolAddress(&p_h1,     g_h1);
    cudaGetSymbolAddress(&p_rowptr, g_rowptr);
    cudaGetSymbolAddress(&p_cursor, g_cursor);
    cudaGetSymbolAddress(&p_w0,     g_Wt0);
    cudaGetSymbolAddress(&p_w1,     g_Wt1);
    const float* Wt0 = (const float*)p_w0;
    const float* Wt1 = (const float*)p_w1;

    const size_t SMEM_GEMM = 2 * 4608 * 2 * sizeof(float);  // 73728 B
    cudaFuncSetAttribute(sage_gemm_mma<true, true, false>,
                         cudaFuncAttributeMaxDynamicSharedMemorySize, (int)SMEM_GEMM);
    cudaFuncSetAttribute(sage_gemm_mma<false, false, true>,
                         cudaFuncAttributeMaxDynamicSharedMemorySize, (int)SMEM_GEMM);

    cudaMemsetAsync(p_cnt,  0, (size_t)N * sizeof(int), 0);
    cudaMemsetAsync(p_norm, 0, sizeof(float), 0);

    // weight transposes (independent of CSR)
    wtrans_kernel<<<512, 256>>>(Ws0, Wn0, (float*)p_w0);
    wtrans_kernel<<<512, 256>>>(Ws1, Wn1, (float*)p_w1);

    // CSR build (reused by both layers)
    hist_kernel<<<(E + 255) / 256, 256>>>(edst, E);
    scan_kernel<<<1, 1024>>>(N);
    cudaMemcpyAsync(p_cursor, p_rowptr, (size_t)N * sizeof(int),
                    cudaMemcpyDeviceToDevice, 0);
    fill_kernel<<<(E + 255) / 256, 256>>>(esrc, edst, E);

    int aggB = (N + 3) / 4;
    dim3 ggrid(2, (N + 127) / 128);
    float* h1 = (float*)p_h1;

    // layer 0
    agg_gather<true><<<aggB, 256>>>(emb, input_nodes, N);
    sage_gemm_mma<true, true, false><<<ggrid, 256, SMEM_GEMM>>>(
        emb, input_nodes, Wt0, b0, h1, N);

    // layer 1
    agg_gather<false><<<aggB, 256>>>(h1, nullptr, N);
    sage_gemm_mma<false, false, true><<<ggrid, 256, SMEM_GEMM>>>(
        h1, nullptr, Wt1, b1, out, N);

    long long total4 = ((long long)N * HH) / 4;
    scale_kernel<<<2048, 256>>>(out, total4);
}

// round 6
// speedup vs baseline: 5.6968x; 1.1728x over previous
#include <cuda_runtime.h>
#include <cuda_fp16.h>
#include <math.h>
#include <stdint.h>

#define MAXN 50000
#define MAXE 1600000
#define HH 256

// ---------------------------------------------------------------------------
// Scratch (no allocations allowed anywhere).
// ---------------------------------------------------------------------------
__device__ float  g_agg[(size_t)MAXN * HH];   // mean-aggregated neighbor feats (fp32)
__device__ float  g_h1[(size_t)MAXN * HH];    // layer-0 output fp32 (GEMM1 self term)
__device__ __half g_x16[(size_t)MAXN * HH];   // gathered emb, fp16 (agg0 source)
__device__ __half g_h16[(size_t)MAXN * HH];   // layer-0 output fp16 (agg1 source)
__device__ int    g_cnt[MAXN];
__device__ int    g_rowptr[MAXN + 1];
__device__ int    g_cursor[MAXN];
__device__ int    g_csr_src[MAXE];
__device__ float  g_deginv[MAXN];
__device__ float  g_normsq;
__device__ int    g_bsum[64];
__device__ int    g_boff[64];
// Transposed tf32-rounded weights: Wt[n][k], n=0..255, k=0..511
__device__ float  g_Wt0[256 * 512];
__device__ float  g_Wt1[256 * 512];

__device__ __forceinline__ float tf32r(float x) {
    uint32_t u;
    asm("cvt.rna.tf32.f32 %0, %1;" : "=r"(u) : "f"(x));
    return __uint_as_float(u);
}

__device__ __forceinline__ void mma_tf32(float& c0, float& c1, float& c2, float& c3,
                                         uint32_t a0, uint32_t a1, uint32_t a2, uint32_t a3,
                                         uint32_t b0, uint32_t b1) {
    asm volatile(
        "mma.sync.aligned.m16n8k8.row.col.f32.tf32.tf32.f32 "
        "{%0,%1,%2,%3}, {%4,%5,%6,%7}, {%8,%9}, {%0,%1,%2,%3};"
        : "+f"(c0), "+f"(c1), "+f"(c2), "+f"(c3)
        : "r"(a0), "r"(a1), "r"(a2), "r"(a3), "r"(b0), "r"(b1));
}

// ---------------------------------------------------------------------------
// CSR build: histogram -> 3-stage multi-block scan -> scatter
// ---------------------------------------------------------------------------
__global__ void hist_kernel(const int* __restrict__ edst, int E) {
    int e = blockIdx.x * blockDim.x + threadIdx.x;
    if (e < E) atomicAdd(&g_cnt[edst[e]], 1);
}

__global__ void scan_part(int N) {          // grid NB x 1024: per-block sums
    int i = blockIdx.x * 1024 + threadIdx.x;
    int v = (i < N) ? g_cnt[i] : 0;
    __shared__ int sh[32];
    int lane = threadIdx.x & 31, wid = threadIdx.x >> 5;
    int s = v;
    #pragma unroll
    for (int o = 16; o; o >>= 1) s += __shfl_down_sync(~0u, s, o);
    if (lane == 0) sh[wid] = s;
    __syncthreads();
    if (wid == 0) {
        int t = sh[lane];
        #pragma unroll
        for (int o = 16; o; o >>= 1) t += __shfl_down_sync(~0u, t, o);
        if (lane == 0) g_bsum[blockIdx.x] = t;
    }
}

__global__ void scan_top(int NB) {          // 1 thread: scan of <=64 block sums
    if (threadIdx.x == 0) {
        int acc = 0;
        for (int b = 0; b < NB; b++) { g_boff[b] = acc; acc += g_bsum[b]; }
    }
}

__global__ void scan_final(int N) {         // grid NB x 1024: local scan + offset
    int i = blockIdx.x * 1024 + threadIdx.x;
    int v = (i < N) ? g_cnt[i] : 0;
    int lane = threadIdx.x & 31, wid = threadIdx.x >> 5;
    int inc = v;
    #pragma unroll
    for (int o = 1; o < 32; o <<= 1) {
        int t = __shfl_up_sync(~0u, inc, o);
        if (lane >= o) inc += t;
    }
    __shared__ int sh[32];
    if (lane == 31) sh[wid] = inc;
    __syncthreads();
    if (wid == 0) {
        int t = sh[lane];
        int e = t;
        #pragma unroll
        for (int o = 1; o < 32; o <<= 1) {
            int u = __shfl_up_sync(~0u, e, o);
            if (lane >= o) e += u;
        }
        sh[lane] = e - t;   // exclusive warp offsets
    }
    __syncthreads();
    int exc = g_boff[blockIdx.x] + sh[wid] + inc - v;
    if (i < N) {
        g_rowptr[i] = exc;
        g_cursor[i] = exc;
        g_deginv[i] = 1.0f / fmaxf((float)v, 1.0f);
        if (i == N - 1) g_rowptr[N] = exc + v;
    }
}

__global__ void fill_kernel(const int* __restrict__ esrc,
                            const int* __restrict__ edst, int E) {
    int e = blockIdx.x * blockDim.x + threadIdx.x;
    if (e < E) {
        int pos = atomicAdd(&g_cursor[edst[e]], 1);
        g_csr_src[pos] = esrc[e];
    }
}

// ---------------------------------------------------------------------------
// Weight transpose + tf32 rounding: Wt[n*512 + k] = tf32(Wext[k][n])
// ---------------------------------------------------------------------------
__global__ void wtrans_kernel(const float* __restrict__ Ws,
                              const float* __restrict__ Wn,
                              float* __restrict__ Wt) {
    int i = blockIdx.x * blockDim.x + threadIdx.x;
    if (i >= 256 * 512) return;
    int n = i >> 9;
    int k = i & 511;
    float v = (k < 256) ? Ws[(size_t)k * 256 + n]
                        : Wn[(size_t)(k - 256) * 256 + n];
    Wt[i] = tf32r(v);
}

// ---------------------------------------------------------------------------
// fp16 pre-gather of emb: g_x16[row] = fp16(emb[idx[row]])
// ---------------------------------------------------------------------------
__global__ void conv16_kernel(const float* __restrict__ emb,
                              const int* __restrict__ idx, int N) {
    int t = blockIdx.x * blockDim.x + threadIdx.x;   // N*64
    int row = t >> 6;
    if (row >= N) return;
    int c = (t & 63) * 4;
    int ar = __ldg(idx + row);
    float4 v = *reinterpret_cast<const float4*>(emb + (size_t)ar * 256 + c);
    __half2 h0 = __floats2half2_rn(v.x, v.y);
    __half2 h1 = __floats2half2_rn(v.z, v.w);
    uint2 packed = make_uint2(*(uint32_t*)&h0, *(uint32_t*)&h1);
    *reinterpret_cast<uint2*>(g_x16 + (size_t)row * HH + c) = packed;
}

// ---------------------------------------------------------------------------
// fp16 gather-based mean aggregation: g_agg[n] = mean fp32( feat16[nbrs] )
// 64 threads per node (4 halfs = 8B per thread), 4 nodes per block.
// ---------------------------------------------------------------------------
__global__ __launch_bounds__(256, 8)
void agg_gather16(const __half* __restrict__ feat16, int N)
{
    int node = blockIdx.x * 4 + (threadIdx.x >> 6);
    if (node >= N) return;
    int c = (threadIdx.x & 63) * 4;

    int b = g_rowptr[node];
    int e = g_rowptr[node + 1];

    float4 acc = make_float4(0.f, 0.f, 0.f, 0.f);
    int i = b;
    for (; i + 4 <= e; i += 4) {
        int s0 = g_csr_src[i + 0];
        int s1 = g_csr_src[i + 1];
        int s2 = g_csr_src[i + 2];
        int s3 = g_csr_src[i + 3];
        uint2 r0 = *reinterpret_cast<const uint2*>(feat16 + (size_t)s0 * HH + c);
        uint2 r1 = *reinterpret_cast<const uint2*>(feat16 + (size_t)s1 * HH + c);
        uint2 r2 = *reinterpret_cast<const uint2*>(feat16 + (size_t)s2 * HH + c);
        uint2 r3 = *reinterpret_cast<const uint2*>(feat16 + (size_t)s3 * HH + c);
        float2 a0 = __half22float2(*(__half2*)&r0.x), b0f = __half22float2(*(__half2*)&r0.y);
        float2 a1 = __half22float2(*(__half2*)&r1.x), b1f = __half22float2(*(__half2*)&r1.y);
        float2 a2 = __half22float2(*(__half2*)&r2.x), b2f = __half22float2(*(__half2*)&r2.y);
        float2 a3 = __half22float2(*(__half2*)&r3.x), b3f = __half22float2(*(__half2*)&r3.y);
        acc.x += (a0.x + a1.x) + (a2.x + a3.x);
        acc.y += (a0.y + a1.y) + (a2.y + a3.y);
        acc.z += (b0f.x + b1f.x) + (b2f.x + b3f.x);
        acc.w += (b0f.y + b1f.y) + (b2f.y + b3f.y);
    }
    for (; i < e; i++) {
        int s = g_csr_src[i];
        uint2 r = *reinterpret_cast<const uint2*>(feat16 + (size_t)s * HH + c);
        float2 a = __half22float2(*(__half2*)&r.x);
        float2 bb = __half22float2(*(__half2*)&r.y);
        acc.x += a.x; acc.y += a.y; acc.z += bb.x; acc.w += bb.y;
    }

    float dv = g_deginv[node];
    acc.x *= dv; acc.y *= dv; acc.z *= dv; acc.w *= dv;
    *reinterpret_cast<float4*>(g_agg + (size_t)node * HH + c) = acc;
}

// ---------------------------------------------------------------------------
// tf32 mma.sync fused SAGE GEMM (unchanged core from R5; +fp16 dual output)
// ---------------------------------------------------------------------------
template<bool USEIDX, bool RELU, bool SUMSQ, bool H16OUT>
__global__ __launch_bounds__(256)
void sage_gemm_mma(const float* __restrict__ Afeat, const int* __restrict__ idx,
                   const float* __restrict__ Wt, const float* __restrict__ bias,
                   float* __restrict__ Cout, int N)
{
    extern __shared__ float sm[];

    const int tid  = threadIdx.x;
    const int wid  = tid >> 5;
    const int lane = tid & 31;
    const int g    = lane >> 2;
    const int t    = lane & 3;
    const int rowbase = blockIdx.y * 128;
    const int colbase = blockIdx.x * 128;

    const int wm = (wid >> 2) * 64;
    const int wn = (wid & 3) * 32;

    const int lr = tid >> 3;
    const int lq = tid & 7;

    float c[4][4][4];
    #pragma unroll
    for (int mt = 0; mt < 4; mt++)
        #pragma unroll
        for (int nt = 0; nt < 4; nt++)
            #pragma unroll
            for (int j = 0; j < 4; j++) c[mt][nt][j] = 0.0f;

    int aoff[4], boff[4];
    #pragma unroll
    for (int mt = 0; mt < 4; mt++) aoff[mt] = (wm + mt * 16 + g) * 36 + t;
    #pragma unroll
    for (int nt = 0; nt < 4; nt++) boff[nt] = (wn + nt * 8 + g) * 36 + t;

    float4 aR[4], bR[4];

    auto load_tile = [&](int kt) {
        const int k0 = kt * 32;
        const bool neigh = (k0 >= 256);
        const float* src = neigh ? (const float*)g_agg : Afeat;
        const int kk = neigh ? (k0 - 256) : k0;
        #pragma unroll
        for (int i = 0; i < 4; i++) {
            int r = lr + i * 32;
            int row = rowbase + r;
            float4 v = make_float4(0.f, 0.f, 0.f, 0.f);
            if (row < N) {
                int ar = (!neigh && USEIDX) ? __ldg(idx + row) : row;
                v = *reinterpret_cast<const float4*>(src + (size_t)ar * 256 + kk + lq * 4);
            }
            aR[i] = v;
        }
        #pragma unroll
        for (int i = 0; i < 4; i++) {
            int r = lr + i * 32;
            bR[i] = *reinterpret_cast<const float4*>(
                Wt + (size_t)(colbase + r) * 512 + k0 + lq * 4);
        }
    };

    auto store_tile = [&](int buf) {
        float* SA = sm + buf * 4608;
        float* SB = sm + 9216 + buf * 4608;
        #pragma unroll
        for (int i = 0; i < 4; i++) {
            int r = lr + i * 32;
            float4 v = aR[i];
            v.x = tf32r(v.x); v.y = tf32r(v.y); v.z = tf32r(v.z); v.w = tf32r(v.w);
            *reinterpret_cast<float4*>(SA + r * 36 + lq * 4) = v;
        }
        #pragma unroll
        for (int i = 0; i < 4; i++) {
            int r = lr + i * 32;
            *reinterpret_cast<float4*>(SB + r * 36 + lq * 4) = bR[i];
        }
    };

    load_tile(0);
    store_tile(0);
    __syncthreads();

    #pragma unroll 1
    for (int kt = 0; kt < 16; kt++) {
        const int buf = kt & 1;
        if (kt + 1 < 16) load_tile(kt + 1);

        const float* SA = sm + buf * 4608;
        const float* SB = sm + 9216 + buf * 4608;

        #pragma unroll
        for (int ks = 0; ks < 4; ks++) {
            const int kb = ks * 8;
            uint32_t af[4][4], bf[4][2];
            #pragma unroll
            for (int mt = 0; mt < 4; mt++) {
                af[mt][0] = __float_as_uint(SA[aoff[mt] + kb]);
                af[mt][1] = __float_as_uint(SA[aoff[mt] + kb + 288]);
                af[mt][2] = __float_as_uint(SA[aoff[mt] + kb + 4]);
                af[mt][3] = __float_as_uint(SA[aoff[mt] + kb + 292]);
            }
            #pragma unroll
            for (int nt = 0; nt < 4; nt++) {
                bf[nt][0] = __float_as_uint(SB[boff[nt] + kb]);
                bf[nt][1] = __float_as_uint(SB[boff[nt] + kb + 4]);
            }
            #pragma unroll
            for (int mt = 0; mt < 4; mt++)
                #pragma unroll
                for (int nt = 0; nt < 4; nt++)
                    mma_tf32(c[mt][nt][0], c[mt][nt][1], c[mt][nt][2], c[mt][nt][3],
                             af[mt][0], af[mt][1], af[mt][2], af[mt][3],
                             bf[nt][0], bf[nt][1]);
        }

        if (kt + 1 < 16) {
            store_tile((kt + 1) & 1);
            __syncthreads();
        }
    }

    // ---- epilogue ----
    float ss = 0.0f;
    #pragma unroll
    for (int nt = 0; nt < 4; nt++) {
        int col = colbase + wn + nt * 8 + 2 * t;
        float2 bv = *reinterpret_cast<const float2*>(bias + col);
        #pragma unroll
        for (int mt = 0; mt < 4; mt++) {
            int r0 = rowbase + wm + mt * 16 + g;
            float x0 = c[mt][nt][0] + bv.x;
            float x1 = c[mt][nt][1] + bv.y;
            float x2 = c[mt][nt][2] + bv.x;
            float x3 = c[mt][nt][3] + bv.y;
            if (RELU) { x0 = fmaxf(x0, 0.f); x1 = fmaxf(x1, 0.f);
                        x2 = fmaxf(x2, 0.f); x3 = fmaxf(x3, 0.f); }
            if (r0 < N) {
                *reinterpret_cast<float2*>(Cout + (size_t)r0 * 256 + col) =
                    make_float2(x0, x1);
                if (H16OUT) {
                    __half2 h = __floats2half2_rn(x0, x1);
                    *reinterpret_cast<__half2*>(g_h16 + (size_t)r0 * 256 + col) = h;
                }
                if (SUMSQ) { ss = fmaf(x0, x0, ss); ss = fmaf(x1, x1, ss); }
            }
            if (r0 + 8 < N) {
                *reinterpret_cast<float2*>(Cout + (size_t)(r0 + 8) * 256 + col) =
                    make_float2(x2, x3);
                if (H16OUT) {
                    __half2 h = __floats2half2_rn(x2, x3);
                    *reinterpret_cast<__half2*>(g_h16 + (size_t)(r0 + 8) * 256 + col) = h;
                }
                if (SUMSQ) { ss = fmaf(x2, x2, ss); ss = fmaf(x3, x3, ss); }
            }
        }
    }

    if (SUMSQ) {
        #pragma unroll
        for (int off = 16; off; off >>= 1)
            ss += __shfl_down_sync(0xffffffffu, ss, off);
        if (lane == 0) atomicAdd(&g_normsq, ss);
    }
}

// ---------------------------------------------------------------------------
__global__ void scale_kernel(float* __restrict__ out, long long total4) {
    float s = 1.0f / sqrtf(g_normsq);
    long long stride = (long long)gridDim.x * blockDim.x;
    for (long long i = (long long)blockIdx.x * blockDim.x + threadIdx.x;
         i < total4; i += stride) {
        float4 v = reinterpret_cast<float4*>(out)[i];
        v.x *= s; v.y *= s; v.z *= s; v.w *= s;
        reinterpret_cast<float4*>(out)[i] = v;
    }
}

// ---------------------------------------------------------------------------
extern "C" void kernel_launch(void* const* d_in, const int* in_sizes, int n_in,
                              void* d_out, int out_size) {
    const int*   input_nodes = (const int*)  d_in[0];
    const int*   esrc        = (const int*)  d_in[1];
    const int*   edst        = (const int*)  d_in[2];
    const float* emb         = (const float*)d_in[3];
    const float* Ws0         = (const float*)d_in[4];
    const float* Wn0         = (const float*)d_in[5];
    const float* b0          = (const float*)d_in[6];
    const float* Ws1         = (const float*)d_in[7];
    const float* Wn1         = (const float*)d_in[8];
    const float* b1          = (const float*)d_in[9];

    int N = in_sizes[0];
    int E = in_sizes[1];
    float* out = (float*)d_out;

    void *p_cnt, *p_norm, *p_h1, *p_w0, *p_w1, *p_x16;
    cudaGetSymbolAddress(&p_cnt,  g_cnt);
    cudaGetSymbolAddress(&p_norm, g_normsq);
    cudaGetSymbolAddress(&p_h1,   g_h1);
    cudaGetSymbolAddress(&p_w0,   g_Wt0);
    cudaGetSymbolAddress(&p_w1,   g_Wt1);
    cudaGetSymbolAddress(&p_x16,  g_x16);
    const float* Wt0 = (const float*)p_w0;
    const float* Wt1 = (const float*)p_w1;
    float* h1 = (float*)p_h1;
    const __half* x16 = (const __half*)p_x16;

    void* p_h16;
    cudaGetSymbolAddress(&p_h16, g_h16);
    const __half* h16 = (const __half*)p_h16;

    const size_t SMEM_GEMM = 2 * 4608 * 2 * sizeof(float);  // 73728 B
    cudaFuncSetAttribute(sage_gemm_mma<true, true, false, true>,
                         cudaFuncAttributeMaxDynamicSharedMemorySize, (int)SMEM_GEMM);
    cudaFuncSetAttribute(sage_gemm_mma<false, false, true, false>,
                         cudaFuncAttributeMaxDynamicSharedMemorySize, (int)SMEM_GEMM);

    cudaMemsetAsync(p_cnt,  0, (size_t)N * sizeof(int), 0);
    cudaMemsetAsync(p_norm, 0, sizeof(float), 0);

    // independent prep
    wtrans_kernel<<<512, 256>>>(Ws0, Wn0, (float*)p_w0);
    wtrans_kernel<<<512, 256>>>(Ws1, Wn1, (float*)p_w1);
    conv16_kernel<<<(N * 64 + 255) / 256, 256>>>(emb, input_nodes, N);

    // CSR build
    int NB = (N + 1023) / 1024;
    hist_kernel<<<(E + 255) / 256, 256>>>(edst, E);
    scan_part<<<NB, 1024>>>(N);
    scan_top<<<1, 32>>>(NB);
    scan_final<<<NB, 1024>>>(N);
    fill_kernel<<<(E + 255) / 256, 256>>>(esrc, edst, E);

    int aggB = (N + 3) / 4;
    dim3 ggrid(2, (N + 127) / 128);

    // layer 0
    agg_gather16<<<aggB, 256>>>(x16, N);
    sage_gemm_mma<true, true, false, true><<<ggrid, 256, SMEM_GEMM>>>(
        emb, input_nodes, Wt0, b0, h1, N);

    // layer 1
    agg_gather16<<<aggB, 256>>>(h16, N);
    sage_gemm_mma<false, false, true, false><<<ggrid, 256, SMEM_GEMM>>>(
        h1, nullptr, Wt1, b1, out, N);

    long long total4 = ((long long)N * HH) / 4;
    scale_kernel<<<2048, 256>>>(out, total4);
}

// round 7
// speedup vs baseline: 7.0749x; 1.2419x over previous
#include <cuda_runtime.h>
#include <cuda_fp16.h>
#include <math.h>
#include <stdint.h>

#define MAXN 50000
#define MAXE 1600000
#define HH 256

// ---------------------------------------------------------------------------
// Scratch (no allocations allowed anywhere).
// ---------------------------------------------------------------------------
__device__ __half g_agg16[(size_t)MAXN * HH]; // mean-aggregated neighbor feats (fp16)
__device__ __half g_x16[(size_t)MAXN * HH];   // gathered emb, fp16
__device__ __half g_h16[(size_t)MAXN * HH];   // layer-0 output, fp16
__device__ int    g_cnt[MAXN];
__device__ int    g_rowptr[MAXN + 1];
__device__ int    g_cursor[MAXN];
__device__ int    g_csr_src[MAXE];
__device__ float  g_deginv[MAXN];
__device__ float  g_normsq;
__device__ int    g_bsum[64];
__device__ int    g_boff[64];
// Transposed fp16 weights: Wt[n][k], n=0..255, k=0..511
__device__ __half g_Wt0[256 * 512];
__device__ __half g_Wt1[256 * 512];

__device__ __forceinline__ void mma_f16(float& c0, float& c1, float& c2, float& c3,
                                        uint32_t a0, uint32_t a1, uint32_t a2, uint32_t a3,
                                        uint32_t b0, uint32_t b1) {
    asm volatile(
        "mma.sync.aligned.m16n8k16.row.col.f32.f16.f16.f32 "
        "{%0,%1,%2,%3}, {%4,%5,%6,%7}, {%8,%9}, {%0,%1,%2,%3};"
        : "+f"(c0), "+f"(c1), "+f"(c2), "+f"(c3)
        : "r"(a0), "r"(a1), "r"(a2), "r"(a3), "r"(b0), "r"(b1));
}

// ---------------------------------------------------------------------------
// CSR build: histogram -> 3-stage multi-block scan -> scatter
// ---------------------------------------------------------------------------
__global__ void hist_kernel(const int* __restrict__ edst, int E) {
    int e = blockIdx.x * blockDim.x + threadIdx.x;
    if (e < E) atomicAdd(&g_cnt[edst[e]], 1);
}

__global__ void scan_part(int N) {
    int i = blockIdx.x * 1024 + threadIdx.x;
    int v = (i < N) ? g_cnt[i] : 0;
    __shared__ int sh[32];
    int lane = threadIdx.x & 31, wid = threadIdx.x >> 5;
    int s = v;
    #pragma unroll
    for (int o = 16; o; o >>= 1) s += __shfl_down_sync(~0u, s, o);
    if (lane == 0) sh[wid] = s;
    __syncthreads();
    if (wid == 0) {
        int t = sh[lane];
        #pragma unroll
        for (int o = 16; o; o >>= 1) t += __shfl_down_sync(~0u, t, o);
        if (lane == 0) g_bsum[blockIdx.x] = t;
    }
}

__global__ void scan_top(int NB) {
    if (threadIdx.x == 0) {
        int acc = 0;
        for (int b = 0; b < NB; b++) { g_boff[b] = acc; acc += g_bsum[b]; }
    }
}

__global__ void scan_final(int N) {
    int i = blockIdx.x * 1024 + threadIdx.x;
    int v = (i < N) ? g_cnt[i] : 0;
    int lane = threadIdx.x & 31, wid = threadIdx.x >> 5;
    int inc = v;
    #pragma unroll
    for (int o = 1; o < 32; o <<= 1) {
        int t = __shfl_up_sync(~0u, inc, o);
        if (lane >= o) inc += t;
    }
    __shared__ int sh[32];
    if (lane == 31) sh[wid] = inc;
    __syncthreads();
    if (wid == 0) {
        int t = sh[lane];
        int e = t;
        #pragma unroll
        for (int o = 1; o < 32; o <<= 1) {
            int u = __shfl_up_sync(~0u, e, o);
            if (lane >= o) e += u;
        }
        sh[lane] = e - t;
    }
    __syncthreads();
    int exc = g_boff[blockIdx.x] + sh[wid] + inc - v;
    if (i < N) {
        g_rowptr[i] = exc;
        g_cursor[i] = exc;
        g_deginv[i] = 1.0f / fmaxf((float)v, 1.0f);
        if (i == N - 1) g_rowptr[N] = exc + v;
    }
}

__global__ void fill_kernel(const int* __restrict__ esrc,
                            const int* __restrict__ edst, int E) {
    int e = blockIdx.x * blockDim.x + threadIdx.x;
    if (e < E) {
        int pos = atomicAdd(&g_cursor[edst[e]], 1);
        g_csr_src[pos] = esrc[e];
    }
}

// ---------------------------------------------------------------------------
// Weight transpose to fp16: Wt16[n*512 + k] = (half)Wext[k][n]
// ---------------------------------------------------------------------------
__global__ void wtrans_kernel(const float* __restrict__ Ws,
                              const float* __restrict__ Wn,
                              __half* __restrict__ Wt) {
    int i = blockIdx.x * blockDim.x + threadIdx.x;
    if (i >= 256 * 512) return;
    int n = i >> 9;
    int k = i & 511;
    float v = (k < 256) ? Ws[(size_t)k * 256 + n]
                        : Wn[(size_t)(k - 256) * 256 + n];
    Wt[i] = __float2half_rn(v);
}

// ---------------------------------------------------------------------------
// fp16 pre-gather of emb: g_x16[row] = fp16(emb[idx[row]])
// ---------------------------------------------------------------------------
__global__ void conv16_kernel(const float* __restrict__ emb,
                              const int* __restrict__ idx, int N) {
    int t = blockIdx.x * blockDim.x + threadIdx.x;
    int row = t >> 6;
    if (row >= N) return;
    int c = (t & 63) * 4;
    int ar = __ldg(idx + row);
    float4 v = *reinterpret_cast<const float4*>(emb + (size_t)ar * 256 + c);
    __half2 h0 = __floats2half2_rn(v.x, v.y);
    __half2 h1 = __floats2half2_rn(v.z, v.w);
    uint2 packed = make_uint2(*(uint32_t*)&h0, *(uint32_t*)&h1);
    *reinterpret_cast<uint2*>(g_x16 + (size_t)row * HH + c) = packed;
}

// ---------------------------------------------------------------------------
// fp16 gather-based mean aggregation -> fp16 output
// ---------------------------------------------------------------------------
__global__ __launch_bounds__(256, 8)
void agg_gather16(const __half* __restrict__ feat16, int N)
{
    int node = blockIdx.x * 4 + (threadIdx.x >> 6);
    if (node >= N) return;
    int c = (threadIdx.x & 63) * 4;

    int b = g_rowptr[node];
    int e = g_rowptr[node + 1];

    float4 acc = make_float4(0.f, 0.f, 0.f, 0.f);
    int i = b;
    for (; i + 4 <= e; i += 4) {
        int s0 = g_csr_src[i + 0];
        int s1 = g_csr_src[i + 1];
        int s2 = g_csr_src[i + 2];
        int s3 = g_csr_src[i + 3];
        uint2 r0 = *reinterpret_cast<const uint2*>(feat16 + (size_t)s0 * HH + c);
        uint2 r1 = *reinterpret_cast<const uint2*>(feat16 + (size_t)s1 * HH + c);
        uint2 r2 = *reinterpret_cast<const uint2*>(feat16 + (size_t)s2 * HH + c);
        uint2 r3 = *reinterpret_cast<const uint2*>(feat16 + (size_t)s3 * HH + c);
        float2 a0 = __half22float2(*(__half2*)&r0.x), b0f = __half22float2(*(__half2*)&r0.y);
        float2 a1 = __half22float2(*(__half2*)&r1.x), b1f = __half22float2(*(__half2*)&r1.y);
        float2 a2 = __half22float2(*(__half2*)&r2.x), b2f = __half22float2(*(__half2*)&r2.y);
        float2 a3 = __half22float2(*(__half2*)&r3.x), b3f = __half22float2(*(__half2*)&r3.y);
        acc.x += (a0.x + a1.x) + (a2.x + a3.x);
        acc.y += (a0.y + a1.y) + (a2.y + a3.y);
        acc.z += (b0f.x + b1f.x) + (b2f.x + b3f.x);
        acc.w += (b0f.y + b1f.y) + (b2f.y + b3f.y);
    }
    for (; i < e; i++) {
        int s = g_csr_src[i];
        uint2 r = *reinterpret_cast<const uint2*>(feat16 + (size_t)s * HH + c);
        float2 a = __half22float2(*(__half2*)&r.x);
        float2 bb = __half22float2(*(__half2*)&r.y);
        acc.x += a.x; acc.y += a.y; acc.z += bb.x; acc.w += bb.y;
    }

    float dv = g_deginv[node];
    __half2 h0 = __floats2half2_rn(acc.x * dv, acc.y * dv);
    __half2 h1 = __floats2half2_rn(acc.z * dv, acc.w * dv);
    uint2 packed = make_uint2(*(uint32_t*)&h0, *(uint32_t*)&h1);
    *reinterpret_cast<uint2*>(g_agg16 + (size_t)node * HH + c) = packed;
}

// ---------------------------------------------------------------------------
// fp16 mma.sync fused SAGE GEMM.
//   C[128-tile, 128-tile] = [self16 | agg16] (K=512) @ Wt16 + bias
// 256 threads = 8 warps (2x4), warp tile 64x32, mma m16n8k16, BK=32,
// double-buffered SMEM fp16 (row stride 40 halfs => conflict-free LDS.32).
// SMEM halfs: A0[0..5119] A1[5120..10239] B0[10240..15359] B1[15360..20479]
// ---------------------------------------------------------------------------
template<bool RELU, bool SUMSQ, bool OUT16>
__global__ __launch_bounds__(256)
void sage_gemm_mma16(const __half* __restrict__ Self16,
                     const __half* __restrict__ Wt,
                     const float* __restrict__ bias,
                     float* __restrict__ Cout, int N)
{
    extern __shared__ __half sm16[];

    const int tid  = threadIdx.x;
    const int wid  = tid >> 5;
    const int lane = tid & 31;
    const int g    = lane >> 2;
    const int t    = lane & 3;
    const int rowbase = blockIdx.y * 128;
    const int colbase = blockIdx.x * 128;

    const int wm = (wid >> 2) * 64;
    const int wn = (wid & 3) * 32;

    const int lr = tid >> 1;          // 0..127 (row)
    const int lq = tid & 1;           // 0..1 (uint4 = 8 halfs within 32-half row: 2 left after pairs)
    // each thread loads 2 uint4 per tile per operand: rows lr, chunks lq and lq+2

    float c[4][4][4];
    #pragma unroll
    for (int mt = 0; mt < 4; mt++)
        #pragma unroll
        for (int nt = 0; nt < 4; nt++)
            #pragma unroll
            for (int j = 0; j < 4; j++) c[mt][nt][j] = 0.0f;

    // fragment smem offsets (halfs); LDS.32 grabs half-pairs
    int aoff[4], boff[4];
    #pragma unroll
    for (int mt = 0; mt < 4; mt++) aoff[mt] = (wm + mt * 16 + g) * 40 + 2 * t;
    #pragma unroll
    for (int nt = 0; nt < 4; nt++) boff[nt] = (wn + nt * 8 + g) * 40 + 2 * t;

    uint4 aR[2], bR[2];

    auto load_tile = [&](int kt) {
        const int k0 = kt * 32;
        const bool neigh = (k0 >= 256);
        const __half* src = neigh ? (const __half*)g_agg16 : Self16;
        const int kk = neigh ? (k0 - 256) : k0;
        int row = rowbase + lr;
        #pragma unroll
        for (int i = 0; i < 2; i++) {
            int q = lq + i * 2;            // 0..3, 8 halfs each
            uint4 v = make_uint4(0, 0, 0, 0);
            if (row < N)
                v = *reinterpret_cast<const uint4*>(src + (size_t)row * 256 + kk + q * 8);
            aR[i] = v;
        }
        #pragma unroll
        for (int i = 0; i < 2; i++) {
            int q = lq + i * 2;
            bR[i] = *reinterpret_cast<const uint4*>(
                Wt + (size_t)(colbase + lr) * 512 + k0 + q * 8);
        }
    };

    auto store_tile = [&](int buf) {
        __half* SA = sm16 + buf * 5120;
        __half* SB = sm16 + 10240 + buf * 5120;
        #pragma unroll
        for (int i = 0; i < 2; i++) {
            int q = lq + i * 2;
            *reinterpret_cast<uint4*>(SA + lr * 40 + q * 8) = aR[i];
        }
        #pragma unroll
        for (int i = 0; i < 2; i++) {
            int q = lq + i * 2;
            *reinterpret_cast<uint4*>(SB + lr * 40 + q * 8) = bR[i];
        }
    };

    load_tile(0);
    store_tile(0);
    __syncthreads();

    #pragma unroll 1
    for (int kt = 0; kt < 16; kt++) {
        const int buf = kt & 1;
        if (kt + 1 < 16) load_tile(kt + 1);

        const __half* SA = sm16 + buf * 5120;
        const __half* SB = sm16 + 10240 + buf * 5120;

        #pragma unroll
        for (int ks = 0; ks < 2; ks++) {
            const int kb = ks * 16;
            uint32_t af[4][4], bf[4][2];
            #pragma unroll
            for (int mt = 0; mt < 4; mt++) {
                af[mt][0] = *reinterpret_cast<const uint32_t*>(SA + aoff[mt] + kb);        // (g,   2t..2t+1)
                af[mt][1] = *reinterpret_cast<const uint32_t*>(SA + aoff[mt] + kb + 320);  // (g+8, 2t..)
                af[mt][2] = *reinterpret_cast<const uint32_t*>(SA + aoff[mt] + kb + 8);    // (g,   2t+8..)
                af[mt][3] = *reinterpret_cast<const uint32_t*>(SA + aoff[mt] + kb + 328);  // (g+8, 2t+8..)
            }
            #pragma unroll
            for (int nt = 0; nt < 4; nt++) {
                bf[nt][0] = *reinterpret_cast<const uint32_t*>(SB + boff[nt] + kb);        // (k=2t..,   n=g)
                bf[nt][1] = *reinterpret_cast<const uint32_t*>(SB + boff[nt] + kb + 8);    // (k=2t+8.., n=g)
            }
            #pragma unroll
            for (int mt = 0; mt < 4; mt++)
                #pragma unroll
                for (int nt = 0; nt < 4; nt++)
                    mma_f16(c[mt][nt][0], c[mt][nt][1], c[mt][nt][2], c[mt][nt][3],
                            af[mt][0], af[mt][1], af[mt][2], af[mt][3],
                            bf[nt][0], bf[nt][1]);
        }

        if (kt + 1 < 16) {
            store_tile((kt + 1) & 1);
            __syncthreads();
        }
    }

    // ---- epilogue ----
    float ss = 0.0f;
    #pragma unroll
    for (int nt = 0; nt < 4; nt++) {
        int col = colbase + wn + nt * 8 + 2 * t;
        float2 bv = *reinterpret_cast<const float2*>(bias + col);
        #pragma unroll
        for (int mt = 0; mt < 4; mt++) {
            int r0 = rowbase + wm + mt * 16 + g;
            float x0 = c[mt][nt][0] + bv.x;
            float x1 = c[mt][nt][1] + bv.y;
            float x2 = c[mt][nt][2] + bv.x;
            float x3 = c[mt][nt][3] + bv.y;
            if (RELU) { x0 = fmaxf(x0, 0.f); x1 = fmaxf(x1, 0.f);
                        x2 = fmaxf(x2, 0.f); x3 = fmaxf(x3, 0.f); }
            if (r0 < N) {
                if (OUT16) {
                    __half2 h = __floats2half2_rn(x0, x1);
                    *reinterpret_cast<__half2*>(g_h16 + (size_t)r0 * 256 + col) = h;
                } else {
                    *reinterpret_cast<float2*>(Cout + (size_t)r0 * 256 + col) =
                        make_float2(x0, x1);
                }
                if (SUMSQ) { ss = fmaf(x0, x0, ss); ss = fmaf(x1, x1, ss); }
            }
            if (r0 + 8 < N) {
                if (OUT16) {
                    __half2 h = __floats2half2_rn(x2, x3);
                    *reinterpret_cast<__half2*>(g_h16 + (size_t)(r0 + 8) * 256 + col) = h;
                } else {
                    *reinterpret_cast<float2*>(Cout + (size_t)(r0 + 8) * 256 + col) =
                        make_float2(x2, x3);
                }
                if (SUMSQ) { ss = fmaf(x2, x2, ss); ss = fmaf(x3, x3, ss); }
            }
        }
    }

    if (SUMSQ) {
        #pragma unroll
        for (int off = 16; off; off >>= 1)
            ss += __shfl_down_sync(0xffffffffu, ss, off);
        if (lane == 0) atomicAdd(&g_normsq, ss);
    }
}

// ---------------------------------------------------------------------------
__global__ void scale_kernel(float* __restrict__ out, long long total4) {
    float s = 1.0f / sqrtf(g_normsq);
    long long stride = (long long)gridDim.x * blockDim.x;
    for (long long i = (long long)blockIdx.x * blockDim.x + threadIdx.x;
         i < total4; i += stride) {
        float4 v = reinterpret_cast<float4*>(out)[i];
        v.x *= s; v.y *= s; v.z *= s; v.w *= s;
        reinterpret_cast<float4*>(out)[i] = v;
    }
}

// ---------------------------------------------------------------------------
extern "C" void kernel_launch(void* const* d_in, const int* in_sizes, int n_in,
                              void* d_out, int out_size) {
    const int*   input_nodes = (const int*)  d_in[0];
    const int*   esrc        = (const int*)  d_in[1];
    const int*   edst        = (const int*)  d_in[2];
    const float* emb         = (const float*)d_in[3];
    const float* Ws0         = (const float*)d_in[4];
    const float* Wn0         = (const float*)d_in[5];
    const float* b0          = (const float*)d_in[6];
    const float* Ws1         = (const float*)d_in[7];
    const float* Wn1         = (const float*)d_in[8];
    const float* b1          = (const float*)d_in[9];

    int N = in_sizes[0];
    int E = in_sizes[1];
    float* out = (float*)d_out;

    void *p_cnt, *p_norm, *p_w0, *p_w1, *p_x16, *p_h16;
    cudaGetSymbolAddress(&p_cnt,  g_cnt);
    cudaGetSymbolAddress(&p_norm, g_normsq);
    cudaGetSymbolAddress(&p_w0,   g_Wt0);
    cudaGetSymbolAddress(&p_w1,   g_Wt1);
    cudaGetSymbolAddress(&p_x16,  g_x16);
    cudaGetSymbolAddress(&p_h16,  g_h16);
    const __half* Wt0 = (const __half*)p_w0;
    const __half* Wt1 = (const __half*)p_w1;
    const __half* x16 = (const __half*)p_x16;
    const __half* h16 = (const __half*)p_h16;

    const size_t SMEM_GEMM = 20480 * sizeof(__half);  // 40960 B
    cudaFuncSetAttribute(sage_gemm_mma16<true, false, true>,
                         cudaFuncAttributeMaxDynamicSharedMemorySize, (int)SMEM_GEMM);
    cudaFuncSetAttribute(sage_gemm_mma16<false, true, false>,
                         cudaFuncAttributeMaxDynamicSharedMemorySize, (int)SMEM_GEMM);

    cudaMemsetAsync(p_cnt,  0, (size_t)N * sizeof(int), 0);
    cudaMemsetAsync(p_norm, 0, sizeof(float), 0);

    // independent prep
    wtrans_kernel<<<512, 256>>>(Ws0, Wn0, (__half*)p_w0);
    wtrans_kernel<<<512, 256>>>(Ws1, Wn1, (__half*)p_w1);
    conv16_kernel<<<(N * 64 + 255) / 256, 256>>>(emb, input_nodes, N);

    // CSR build
    int NB = (N + 1023) / 1024;
    hist_kernel<<<(E + 255) / 256, 256>>>(edst, E);
    scan_part<<<NB, 1024>>>(N);
    scan_top<<<1, 32>>>(NB);
    scan_final<<<NB, 1024>>>(N);
    fill_kernel<<<(E + 255) / 256, 256>>>(esrc, edst, E);

    int aggB = (N + 3) / 4;
    dim3 ggrid(2, (N + 127) / 128);

    // layer 0: agg(emb16) -> GEMM -> h16
    agg_gather16<<<aggB, 256>>>(x16, N);
    sage_gemm_mma16<true, false, true><<<ggrid, 256, SMEM_GEMM>>>(
        x16, Wt0, b0, nullptr, N);

    // layer 1: agg(h16) -> GEMM -> out (fp32) + sumsq
    agg_gather16<<<aggB, 256>>>(h16, N);
    sage_gemm_mma16<false, true, false><<<ggrid, 256, SMEM_GEMM>>>(
        h16, Wt1, b1, out, N);

    long long total4 = ((long long)N * HH) / 4;
    scale_kernel<<<2048, 256>>>(out, total4);
}